// round 1
// baseline (speedup 1.0000x reference)
#include <cuda_runtime.h>
#include <cstdint>

// Problem constants
#define N_ROWS 32768      // B*T = 8*4096
#define D      64
#define K      1024
#define TK     128        // K-tile staged in shared memory
#define BLK    128        // threads per block (1 thread = 1 row)
#define NBLK   (N_ROWS / BLK)   // 256 blocks

// Output layout (flattened tuple order: quantized, encodings, indices, loss)
#define OFF_QUANT 0
#define OFF_ENC   ((size_t)N_ROWS * D)                 // 2,097,152
#define OFF_IDX   (OFF_ENC + (size_t)N_ROWS * K)       // 35,651,584
#define OFF_LOSS  (OFF_IDX + (size_t)N_ROWS)           // 35,684,352

// Scratch (no cudaMalloc allowed)
__device__ float g_esq[K];
__device__ float g_rowloss[N_ROWS];

// ---------------------------------------------------------------------------
// Precompute ||e_k||^2 for each codeword. emb layout: [D, K] row-major.
// ---------------------------------------------------------------------------
__global__ void esq_kernel(const float* __restrict__ emb) {
    int k = blockIdx.x * blockDim.x + threadIdx.x;
    if (k < K) {
        float s = 0.f;
        #pragma unroll
        for (int d = 0; d < D; d++) {
            float e = emb[d * K + k];
            s = fmaf(e, e, s);
        }
        g_esq[k] = s;
    }
}

// ---------------------------------------------------------------------------
// Main kernel: per-row argmin of (esq_k - 2*x.e_k), write quantized, indices,
// one-hot encodings scatter, and per-row loss partials.
// ---------------------------------------------------------------------------
__global__ __launch_bounds__(BLK) void vq_main(const float* __restrict__ x,
                                               const float* __restrict__ emb,
                                               float* __restrict__ out) {
    __shared__ float es[D * TK];     // 32 KB: embeddings K-tile, [d][kt]
    __shared__ float esq_s[TK];      // 512 B

    const int tid  = threadIdx.x;
    const int row  = blockIdx.x * BLK + tid;

    // Load this thread's x row into registers (float4 LDG; uncoalesced across
    // lanes but only ~8MB total, negligible).
    float xr[D];
    {
        const float4* xp = (const float4*)(x + (size_t)row * D);
        #pragma unroll
        for (int i = 0; i < D / 4; i++) {
            float4 v = xp[i];
            xr[i * 4 + 0] = v.x;
            xr[i * 4 + 1] = v.y;
            xr[i * 4 + 2] = v.z;
            xr[i * 4 + 3] = v.w;
        }
    }

    float best = 3.4e38f;
    int   bi   = 0;

    for (int t = 0; t < K / TK; t++) {
        __syncthreads();  // protect smem reuse across tiles
        // Stage embeddings tile [D x TK]: coalesced float4 loads.
        // D*TK/4 = 2048 float4s, 128 threads -> 16 each.
        const float* embt = emb + t * TK;
        #pragma unroll
        for (int i = 0; i < (D * TK / 4) / BLK; i++) {
            int j  = i * BLK + tid;       // float4 index
            int e0 = j * 4;
            int d  = e0 / TK;
            int kt = e0 % TK;
            float4 v = *(const float4*)(embt + (size_t)d * K + kt);
            *(float4*)(es + d * TK + kt) = v;
        }
        if (tid < TK) esq_s[tid] = g_esq[t * TK + tid];
        __syncthreads();

        // Scan tile: 4 codewords at a time, fully unrolled d-loop.
        #pragma unroll 1
        for (int kk = 0; kk < TK; kk += 4) {
            float a0 = 0.f, a1 = 0.f, a2 = 0.f, a3 = 0.f;
            #pragma unroll
            for (int d = 0; d < D; d++) {
                float4 e = *(const float4*)(es + d * TK + kk);
                float xv = xr[d];
                a0 = fmaf(xv, e.x, a0);
                a1 = fmaf(xv, e.y, a1);
                a2 = fmaf(xv, e.z, a2);
                a3 = fmaf(xv, e.w, a3);
            }
            // score = ||e||^2 - 2*sim  (argmin matches argmin of full dist)
            float s0 = fmaf(-2.f, a0, esq_s[kk + 0]);
            float s1 = fmaf(-2.f, a1, esq_s[kk + 1]);
            float s2 = fmaf(-2.f, a2, esq_s[kk + 2]);
            float s3 = fmaf(-2.f, a3, esq_s[kk + 3]);
            int kb = t * TK + kk;
            // strict < in index order => first-min tie-break like jnp.argmax
            if (s0 < best) { best = s0; bi = kb + 0; }
            if (s1 < best) { best = s1; bi = kb + 1; }
            if (s2 < best) { best = s2; bi = kb + 2; }
            if (s3 < best) { best = s3; bi = kb + 3; }
        }
    }

    // --- outputs ---
    // quantized row (gather codeword column) + exact per-row loss partial
    float ls = 0.f;
    const float* ecol = emb + bi;                  // stride K down column
    float* q = out + OFF_QUANT + (size_t)row * D;
    #pragma unroll
    for (int d = 0; d < D; d++) {
        float e = ecol[(size_t)d * K];
        q[d] = e;
        float df = e - xr[d];
        ls = fmaf(df, df, ls);
    }
    g_rowloss[row] = ls;

    // index (cast to float; exact for < 2^24)
    out[OFF_IDX + row] = (float)bi;

    // one-hot scatter into pre-zeroed encodings
    out[OFF_ENC + (size_t)row * K + bi] = 1.0f;
}

// ---------------------------------------------------------------------------
// Deterministic loss reduction: fixed-order strided partials + smem tree.
// ---------------------------------------------------------------------------
__global__ void loss_kernel(float* __restrict__ out) {
    __shared__ double sb[1024];
    int tid = threadIdx.x;
    double s = 0.0;
    for (int i = tid; i < N_ROWS; i += 1024) s += (double)g_rowloss[i];
    sb[tid] = s;
    __syncthreads();
    for (int off = 512; off > 0; off >>= 1) {
        if (tid < off) sb[tid] += sb[tid + off];
        __syncthreads();
    }
    if (tid == 0) {
        out[OFF_LOSS] = (float)(sb[0] / (double)((size_t)N_ROWS * D));
    }
}

// ---------------------------------------------------------------------------
extern "C" void kernel_launch(void* const* d_in, const int* in_sizes, int n_in,
                              void* d_out, int out_size) {
    const float* x   = (const float*)d_in[0];   // [B,T,D] = [8,4096,64]
    const float* emb = (const float*)d_in[1];   // [D,K]   = [64,1024]
    float* out = (float*)d_out;

    // Zero the encodings region (one-hot target). 134 MB, ~17us at HBM bw.
    cudaMemsetAsync(out + OFF_ENC, 0, (size_t)N_ROWS * K * sizeof(float));

    esq_kernel<<<(K + 255) / 256, 256>>>(emb);
    vq_main<<<NBLK, BLK>>>(x, emb, out);
    loss_kernel<<<1, 1024>>>(out);
}

// round 2
// speedup vs baseline: 1.2430x; 1.2430x over previous
#include <cuda_runtime.h>
#include <cstdint>

// Problem constants
#define N_ROWS 32768      // B*T = 8*4096
#define D      64
#define K      1024
#define TK     128        // K-tile staged in shared memory
#define BLK    128        // threads per block (1 thread = 1 row)
#define NBLK   (N_ROWS / BLK)   // 256 blocks

// Output layout (flattened tuple order: quantized, encodings, indices, loss)
#define OFF_QUANT 0
#define OFF_ENC   ((size_t)N_ROWS * D)                 // 2,097,152
#define OFF_IDX   (OFF_ENC + (size_t)N_ROWS * K)       // 35,651,584
#define OFF_LOSS  (OFF_IDX + (size_t)N_ROWS)           // 35,684,352

// Scratch (no cudaMalloc allowed)
__device__ float g_rowloss[N_ROWS];

// Packed fp32x2 helpers (sm_103a FFMA2 path — only reachable via PTX f32x2)
#define FMA2(acc, xa, eb) \
    asm("fma.rn.f32x2 %0, %1, %2, %0;" : "+l"(acc) : "l"(xa), "l"(eb))
#define UNPACK2(lo, hi, v) \
    asm("mov.b64 {%0, %1}, %2;" : "=f"(lo), "=f"(hi) : "l"(v))
#define PACK_DUP(dst, v) \
    asm("mov.b64 %0, {%1, %1};" : "=l"(dst) : "f"(v))

// ---------------------------------------------------------------------------
// Main kernel: per-row argmin of (||e_k||^2 - 2*x.e_k) via packed f32x2 FMA.
// Also writes quantized rows, indices, full one-hot encodings (zeros written
// cooperatively per tile, overlapped with compute), and per-row loss partials.
// ---------------------------------------------------------------------------
__global__ __launch_bounds__(BLK, 2) void vq_main(const float* __restrict__ x,
                                                  const float* __restrict__ emb,
                                                  float* __restrict__ out) {
    __shared__ __align__(16) float es[D * TK];   // 32 KB: emb K-tile, [d][kt]
    __shared__ float esq_s[TK];                  // 512 B: ||e||^2 for the tile

    const int tid = threadIdx.x;
    const int row = blockIdx.x * BLK + tid;
    const int warp = tid >> 5, lane = tid & 31;

    // Load this thread's x row; keep only the duplicated-packed form (v,v).
    unsigned long long xp[D];   // 128 regs
    {
        const float4* xpin = (const float4*)(x + (size_t)row * D);
        #pragma unroll
        for (int i = 0; i < D / 4; i++) {
            float4 v = xpin[i];
            PACK_DUP(xp[i * 4 + 0], v.x);
            PACK_DUP(xp[i * 4 + 1], v.y);
            PACK_DUP(xp[i * 4 + 2], v.z);
            PACK_DUP(xp[i * 4 + 3], v.w);
        }
    }

    float best = 3.4e38f;
    int   bi   = 0;

    for (int t = 0; t < K / TK; t++) {
        __syncthreads();  // protect smem reuse across tiles
        // Stage embeddings tile [D x TK]: coalesced float4 loads (16/thread).
        const float* embt = emb + t * TK;
        #pragma unroll
        for (int i = 0; i < (D * TK / 4) / BLK; i++) {
            int j  = i * BLK + tid;       // float4 index
            int e0 = j * 4;
            int d  = e0 / TK;
            int kt = e0 % TK;
            *(float4*)(es + d * TK + kt) =
                *(const float4*)(embt + (size_t)d * K + kt);
        }
        __syncthreads();

        // Per-tile ||e_k||^2 from the staged tile (conflict-free LDS).
        {
            float eq = 0.f;
            #pragma unroll
            for (int d = 0; d < D; d++) {
                float e = es[d * TK + tid];
                eq = fmaf(e, e, eq);
            }
            esq_s[tid] = eq;
        }

        // Cooperative zero-fill of this tile's encodings columns (coalesced,
        // independent gmem traffic — drains under the compute below).
        {
            float4 z = make_float4(0.f, 0.f, 0.f, 0.f);
            float* encbase = out + OFF_ENC
                           + (size_t)(blockIdx.x * BLK) * K + (size_t)t * TK;
            #pragma unroll
            for (int rr = warp; rr < BLK; rr += BLK / 32) {
                *(float4*)(encbase + (size_t)rr * K + lane * 4) = z;
            }
        }
        __syncthreads();  // esq_s ready for all threads

        // Scan tile: 8 codewords per group, packed f32x2 FMA (FFMA2).
        #pragma unroll 1
        for (int kk = 0; kk < TK; kk += 8) {
            unsigned long long a0 = 0ull, a1 = 0ull, a2 = 0ull, a3 = 0ull;
            #pragma unroll
            for (int d = 0; d < D; d++) {
                const ulonglong2* ep = (const ulonglong2*)(es + d * TK + kk);
                ulonglong2 e0 = ep[0];   // k: kk..kk+3
                ulonglong2 e1 = ep[1];   // k: kk+4..kk+7
                FMA2(a0, xp[d], e0.x);
                FMA2(a1, xp[d], e0.y);
                FMA2(a2, xp[d], e1.x);
                FMA2(a3, xp[d], e1.y);
            }
            float s0, s1, s2, s3, s4, s5, s6, s7;
            UNPACK2(s0, s1, a0);
            UNPACK2(s2, s3, a1);
            UNPACK2(s4, s5, a2);
            UNPACK2(s6, s7, a3);
            // score = ||e||^2 - 2*sim (argmin-equivalent to full distance)
            float c0 = fmaf(-2.f, s0, esq_s[kk + 0]);
            float c1 = fmaf(-2.f, s1, esq_s[kk + 1]);
            float c2 = fmaf(-2.f, s2, esq_s[kk + 2]);
            float c3 = fmaf(-2.f, s3, esq_s[kk + 3]);
            float c4 = fmaf(-2.f, s4, esq_s[kk + 4]);
            float c5 = fmaf(-2.f, s5, esq_s[kk + 5]);
            float c6 = fmaf(-2.f, s6, esq_s[kk + 6]);
            float c7 = fmaf(-2.f, s7, esq_s[kk + 7]);
            int kb = t * TK + kk;
            // strict < in index order => first-min tie-break (jnp.argmax)
            if (c0 < best) { best = c0; bi = kb + 0; }
            if (c1 < best) { best = c1; bi = kb + 1; }
            if (c2 < best) { best = c2; bi = kb + 2; }
            if (c3 < best) { best = c3; bi = kb + 3; }
            if (c4 < best) { best = c4; bi = kb + 4; }
            if (c5 < best) { best = c5; bi = kb + 5; }
            if (c6 < best) { best = c6; bi = kb + 6; }
            if (c7 < best) { best = c7; bi = kb + 7; }
        }
    }

    // All cooperative zero-fills done before anyone scatters a 1.0.
    __syncthreads();

    // quantized row (gather codeword column) + exact per-row loss partial
    float ls = 0.f;
    const float* ecol = emb + bi;                  // stride K down column
    float* q = out + OFF_QUANT + (size_t)row * D;
    #pragma unroll
    for (int d = 0; d < D; d++) {
        float e = ecol[(size_t)d * K];
        q[d] = e;
        float xv;
        {   // low half of packed (v,v) is v
            float hi_unused;
            UNPACK2(xv, hi_unused, xp[d]);
        }
        float df = e - xv;
        ls = fmaf(df, df, ls);
    }
    g_rowloss[row] = ls;

    // index (cast to float; exact for < 2^24)
    out[OFF_IDX + row] = (float)bi;

    // one-hot scatter into the zeros this block just wrote
    out[OFF_ENC + (size_t)row * K + bi] = 1.0f;
}

// ---------------------------------------------------------------------------
// Deterministic loss reduction: fixed-order strided partials + smem tree.
// ---------------------------------------------------------------------------
__global__ void loss_kernel(float* __restrict__ out) {
    __shared__ double sb[1024];
    int tid = threadIdx.x;
    double s = 0.0;
    for (int i = tid; i < N_ROWS; i += 1024) s += (double)g_rowloss[i];
    sb[tid] = s;
    __syncthreads();
    for (int off = 512; off > 0; off >>= 1) {
        if (tid < off) sb[tid] += sb[tid + off];
        __syncthreads();
    }
    if (tid == 0) {
        out[OFF_LOSS] = (float)(sb[0] / (double)((size_t)N_ROWS * D));
    }
}

// ---------------------------------------------------------------------------
extern "C" void kernel_launch(void* const* d_in, const int* in_sizes, int n_in,
                              void* d_out, int out_size) {
    const float* x   = (const float*)d_in[0];   // [B,T,D] = [8,4096,64]
    const float* emb = (const float*)d_in[1];   // [D,K]   = [64,1024]
    float* out = (float*)d_out;

    vq_main<<<NBLK, BLK>>>(x, emb, out);
    loss_kernel<<<1, 1024>>>(out);
}